// round 1
// baseline (speedup 1.0000x reference)
#include <cuda_runtime.h>

#define BS 4
#define NS 1024
#define D 2048
#define H 16
#define DHD 128
#define SCALE 0.08838834764831845f
#define MASK_BIAS -1e9f

// ---------------- scratch (static device globals; no allocation) ----------
__device__ float g_q[BS * H * NS * DHD];
__device__ float g_k[BS * H * NS * DHD];
__device__ float g_v[BS * H * NS * DHD];
__device__ float g_o[BS * NS * D];

// ---------------- shared GEMM core: C[M,N] = A[M,K] @ B[N,K]^T ------------
// 128x128 tile, K-slab 8, 256 threads, 8x8 micro-tile per thread.
__device__ __forceinline__ void gemm_tile_core(
    const float* __restrict__ A, const float* __restrict__ B, int K,
    float acc[8][8], float* As, float* Bsh)
{
    const int tid = threadIdx.x;
    const int lr = tid >> 1;            // 0..127
    const int lk = (tid & 1) * 4;       // 0 or 4
    const int ty = tid >> 4;            // 0..15
    const int tx = tid & 15;            // 0..15
    const int row0 = blockIdx.y * 128;
    const int col0 = blockIdx.x * 128;

    for (int k0 = 0; k0 < K; k0 += 8) {
        float4 av = *(const float4*)&A[(row0 + lr) * K + k0 + lk];
        float4 bv = *(const float4*)&B[(col0 + lr) * K + k0 + lk];
        __syncthreads();
        As[(lk + 0) * 128 + lr] = av.x;
        As[(lk + 1) * 128 + lr] = av.y;
        As[(lk + 2) * 128 + lr] = av.z;
        As[(lk + 3) * 128 + lr] = av.w;
        Bsh[(lk + 0) * 128 + lr] = bv.x;
        Bsh[(lk + 1) * 128 + lr] = bv.y;
        Bsh[(lk + 2) * 128 + lr] = bv.z;
        Bsh[(lk + 3) * 128 + lr] = bv.w;
        __syncthreads();
#pragma unroll
        for (int kk = 0; kk < 8; kk++) {
            float a[8], b[8];
            *(float4*)(a)     = *(float4*)&As[kk * 128 + ty * 8];
            *(float4*)(a + 4) = *(float4*)&As[kk * 128 + ty * 8 + 4];
            *(float4*)(b)     = *(float4*)&Bsh[kk * 128 + tx * 8];
            *(float4*)(b + 4) = *(float4*)&Bsh[kk * 128 + tx * 8 + 4];
#pragma unroll
            for (int i = 0; i < 8; i++)
#pragma unroll
                for (int j = 0; j < 8; j++)
                    acc[i][j] += a[i] * b[j];
        }
    }
}

// ---------------- GEMM1: qkv = x @ w_in^T, scattered to q/k/v buffers -----
__global__ void __launch_bounds__(256) gemm_qkv_kernel(
    const float* __restrict__ X, const float* __restrict__ Win)
{
    __shared__ float As[8 * 128];
    __shared__ float Bsh[8 * 128];
    float acc[8][8] = {};
    gemm_tile_core(X, Win, D, acc, As, Bsh);

    const int tid = threadIdx.x;
    const int ty = tid >> 4, tx = tid & 15;
    const int row0 = blockIdx.y * 128;
    const int col0 = blockIdx.x * 128;
    // tile lies entirely within one (which, head): col tile width 128 == DH
    const int which = col0 >> 11;          // 0=q 1=k 2=v
    const int hh = (col0 >> 7) & 15;
    const int bb = row0 >> 10;
    const int s0 = row0 & 1023;
    float* dst = (which == 0) ? g_q : ((which == 1) ? g_k : g_v);
    float* base = dst + ((bb * H + hh) * NS) * DHD;
#pragma unroll
    for (int i = 0; i < 8; i++) {
        int s = s0 + ty * 8 + i;
        float4 v0 = make_float4(acc[i][0], acc[i][1], acc[i][2], acc[i][3]);
        float4 v1 = make_float4(acc[i][4], acc[i][5], acc[i][6], acc[i][7]);
        *(float4*)&base[s * DHD + tx * 8] = v0;
        *(float4*)&base[s * DHD + tx * 8 + 4] = v1;
    }
}

// ---------------- GEMM2: out = o @ w_out^T + b_out ------------------------
__global__ void __launch_bounds__(256) gemm_out_kernel(
    const float* __restrict__ Wout, const float* __restrict__ bout,
    float* __restrict__ C)
{
    __shared__ float As[8 * 128];
    __shared__ float Bsh[8 * 128];
    float acc[8][8] = {};
    gemm_tile_core(g_o, Wout, D, acc, As, Bsh);

    const int tid = threadIdx.x;
    const int ty = tid >> 4, tx = tid & 15;
    const int row0 = blockIdx.y * 128;
    const int col0 = blockIdx.x * 128;
    const int n0 = col0 + tx * 8;
    float4 b0 = *(const float4*)&bout[n0];
    float4 b1 = *(const float4*)&bout[n0 + 4];
#pragma unroll
    for (int i = 0; i < 8; i++) {
        int m = row0 + ty * 8 + i;
        float4 v0 = make_float4(acc[i][0] + b0.x, acc[i][1] + b0.y,
                                acc[i][2] + b0.z, acc[i][3] + b0.w);
        float4 v1 = make_float4(acc[i][4] + b1.x, acc[i][5] + b1.y,
                                acc[i][6] + b1.z, acc[i][7] + b1.w);
        *(float4*)&C[m * D + n0] = v0;
        *(float4*)&C[m * D + n0 + 4] = v1;
    }
}

// ---------------- attention: flash-style, block = (b, h, 64-row q-tile) ---
#define BQ 64
#define BK 64
#define QLD 129
#define KLD 129
#define SLD 65
// smem floats: Qs 64*129 + Ks 64*129 + Vs 64*128 + Ss 64*65 + 4*64
#define ATTN_SMEM_FLOATS (BQ * QLD + BK * KLD + BK * DHD + BQ * SLD + 4 * 64)
#define ATTN_SMEM_BYTES (ATTN_SMEM_FLOATS * 4)

__global__ void __launch_bounds__(256) attn_kernel(const int* __restrict__ ids)
{
    extern __shared__ float sm[];
    float* Qs   = sm;                      // [64][129]
    float* Ks   = Qs + BQ * QLD;           // [64][129]
    float* Vs   = Ks + BK * KLD;           // [64][128]
    float* Ss   = Vs + BK * DHD;           // [64][65]
    float* mrow = Ss + BQ * SLD;           // [64]
    float* lrow = mrow + BQ;               // [64]
    float* crow = lrow + BQ;               // [64]
    float* bks  = crow + BQ;               // [64] key bias

    const int tid = threadIdx.x;
    const int ty = tid >> 4;   // 0..15 -> q rows 4*ty..4*ty+3
    const int tx = tid & 15;   // 0..15 -> cols
    const int qt = blockIdx.x;
    const int h  = blockIdx.y;
    const int b  = blockIdx.z;

    const float* Qg = g_q + ((b * H + h) * NS + qt * BQ) * DHD;
    const float* Kg = g_k + ((b * H + h) * NS) * DHD;
    const float* Vg = g_v + ((b * H + h) * NS) * DHD;

    // load Q tile (64x128) into padded smem
#pragma unroll
    for (int r = 0; r < 8; r++) {
        int idx = tid + 256 * r;
        int s = idx >> 5;
        int d4 = (idx & 31) << 2;
        float4 v = *(const float4*)&Qg[s * DHD + d4];
        Qs[s * QLD + d4 + 0] = v.x;
        Qs[s * QLD + d4 + 1] = v.y;
        Qs[s * QLD + d4 + 2] = v.z;
        Qs[s * QLD + d4 + 3] = v.w;
    }
    if (tid < BQ) { mrow[tid] = -1e30f; lrow[tid] = 0.0f; }

    float oacc[4][8] = {};   // rows 4*ty+i, cols 8*tx+j

    for (int kt = 0; kt < NS / BK; kt++) {
        __syncthreads();  // protect smem from previous iteration's readers
        // load K (padded), V (unpadded), key bias
#pragma unroll
        for (int r = 0; r < 8; r++) {
            int idx = tid + 256 * r;
            int s = idx >> 5;
            int d4 = (idx & 31) << 2;
            float4 kv = *(const float4*)&Kg[(kt * BK + s) * DHD + d4];
            Ks[s * KLD + d4 + 0] = kv.x;
            Ks[s * KLD + d4 + 1] = kv.y;
            Ks[s * KLD + d4 + 2] = kv.z;
            Ks[s * KLD + d4 + 3] = kv.w;
            float4 vv = *(const float4*)&Vg[(kt * BK + s) * DHD + d4];
            *(float4*)&Vs[s * DHD + d4] = vv;
        }
        if (tid < BK)
            bks[tid] = MASK_BIAS * (float)ids[b * NS + kt * BK + tid];
        __syncthreads();

        // scores: S[4ty+i][4tx+j] = dot(Q_row, K_row)
        float sacc[4][4] = {};
#pragma unroll 4
        for (int d = 0; d < DHD; d++) {
            float qv[4], kv[4];
#pragma unroll
            for (int i = 0; i < 4; i++) qv[i] = Qs[(4 * ty + i) * QLD + d];
#pragma unroll
            for (int j = 0; j < 4; j++) kv[j] = Ks[(4 * tx + j) * KLD + d];
#pragma unroll
            for (int i = 0; i < 4; i++)
#pragma unroll
                for (int j = 0; j < 4; j++)
                    sacc[i][j] += qv[i] * kv[j];
        }
#pragma unroll
        for (int i = 0; i < 4; i++)
#pragma unroll
            for (int j = 0; j < 4; j++)
                Ss[(4 * ty + i) * SLD + 4 * tx + j] =
                    (sacc[i][j] + bks[4 * tx + j]) * SCALE;
        __syncthreads();

        // online softmax: one thread per q row
        if (tid < BQ) {
            int r = tid;
            float mold = mrow[r];
            float mmax = mold;
            for (int c = 0; c < BK; c++)
                mmax = fmaxf(mmax, Ss[r * SLD + c]);
            float corr = __expf(mold - mmax);
            float lsum = 0.0f;
            for (int c = 0; c < BK; c++) {
                float p = __expf(Ss[r * SLD + c] - mmax);
                Ss[r * SLD + c] = p;
                lsum += p;
            }
            mrow[r] = mmax;
            lrow[r] = lrow[r] * corr + lsum;
            crow[r] = corr;
        }
        __syncthreads();

        // O = O*corr + P @ V
#pragma unroll
        for (int i = 0; i < 4; i++) {
            float corr = crow[4 * ty + i];
#pragma unroll
            for (int j = 0; j < 8; j++) oacc[i][j] *= corr;
        }
#pragma unroll 4
        for (int kr = 0; kr < BK; kr++) {
            float pv[4];
#pragma unroll
            for (int i = 0; i < 4; i++) pv[i] = Ss[(4 * ty + i) * SLD + kr];
            float4 v0 = *(float4*)&Vs[kr * DHD + 8 * tx];
            float4 v1 = *(float4*)&Vs[kr * DHD + 8 * tx + 4];
#pragma unroll
            for (int i = 0; i < 4; i++) {
                oacc[i][0] += pv[i] * v0.x;
                oacc[i][1] += pv[i] * v0.y;
                oacc[i][2] += pv[i] * v0.z;
                oacc[i][3] += pv[i] * v0.w;
                oacc[i][4] += pv[i] * v1.x;
                oacc[i][5] += pv[i] * v1.y;
                oacc[i][6] += pv[i] * v1.z;
                oacc[i][7] += pv[i] * v1.w;
            }
        }
    }

    // normalize and write O to [b, s, h*DH + c] layout
    float* Og = g_o + (b * NS + qt * BQ) * D + h * DHD;
#pragma unroll
    for (int i = 0; i < 4; i++) {
        int r = 4 * ty + i;
        float linv = 1.0f / lrow[r];
        float4 o0 = make_float4(oacc[i][0] * linv, oacc[i][1] * linv,
                                oacc[i][2] * linv, oacc[i][3] * linv);
        float4 o1 = make_float4(oacc[i][4] * linv, oacc[i][5] * linv,
                                oacc[i][6] * linv, oacc[i][7] * linv);
        *(float4*)&Og[r * D + 8 * tx] = o0;
        *(float4*)&Og[r * D + 8 * tx + 4] = o1;
    }
}

// ---------------- launch ---------------------------------------------------
extern "C" void kernel_launch(void* const* d_in, const int* in_sizes, int n_in,
                              void* d_out, int out_size)
{
    const float* x     = (const float*)d_in[0];
    const int*   ids   = (const int*)d_in[1];
    const float* w_in  = (const float*)d_in[2];
    const float* w_out = (const float*)d_in[3];
    const float* b_out = (const float*)d_in[4];
    float* out = (float*)d_out;

    cudaFuncSetAttribute(attn_kernel,
                         cudaFuncAttributeMaxDynamicSharedMemorySize,
                         ATTN_SMEM_BYTES);

    // GEMM1: M=4096, N=6144, K=2048
    gemm_qkv_kernel<<<dim3(6144 / 128, 4096 / 128), 256>>>(x, w_in);
    // attention: (q_tiles, heads, batch)
    attn_kernel<<<dim3(NS / BQ, H, BS), 256, ATTN_SMEM_BYTES>>>(ids);
    // GEMM2: M=4096, N=2048, K=2048
    gemm_out_kernel<<<dim3(2048 / 128, 4096 / 128), 256>>>(w_out, b_out, out);
}

// round 3
// speedup vs baseline: 1.9467x; 1.9467x over previous
#include <cuda_runtime.h>
#include <cuda_bf16.h>
#include <cstdint>

#define BS 4
#define NS 1024
#define D 2048
#define H 16
#define DHD 128
#define SCALE 0.08838834764831845f
#define MASK_BIAS -1e9f
#define M_ROWS (BS * NS)   /* 4096 */
#define N_QKV (3 * D)      /* 6144 */

// ---------------- scratch (static device globals; no allocation) ----------
__device__ float g_q[BS * H * NS * DHD];
__device__ float g_k[BS * H * NS * DHD];
__device__ float g_v[BS * H * NS * DHD];
__device__ __nv_bfloat16 g_x0[M_ROWS * D],  g_x1[M_ROWS * D];
__device__ __nv_bfloat16 g_wi0[N_QKV * D],  g_wi1[N_QKV * D];
__device__ __nv_bfloat16 g_wo0[D * D],      g_wo1[D * D];
__device__ __nv_bfloat16 g_o0[M_ROWS * D],  g_o1[M_ROWS * D];

// ---------------- helpers ---------------------------------------------------
__device__ __forceinline__ uint32_t smem_to_u32(const void* p) {
    uint32_t a;
    asm("{ .reg .u64 t; cvta.to.shared.u64 t, %1; cvt.u32.u64 %0, t; }"
        : "=r"(a) : "l"(p));
    return a;
}
#define CP_ASYNC16(dst, src) \
    asm volatile("cp.async.cg.shared.global [%0], [%1], 16;" \
                 :: "r"((uint32_t)(dst)), "l"(src) : "memory")
#define CP_COMMIT() asm volatile("cp.async.commit_group;" ::: "memory")
#define CP_WAIT(n)  asm volatile("cp.async.wait_group %0;" :: "n"(n) : "memory")

__device__ __forceinline__ void ldsm4(uint32_t r[4], uint32_t addr) {
    asm volatile("ldmatrix.sync.aligned.m8n8.x4.shared.b16 {%0,%1,%2,%3}, [%4];"
                 : "=r"(r[0]), "=r"(r[1]), "=r"(r[2]), "=r"(r[3]) : "r"(addr));
}
__device__ __forceinline__ void mma16816(float c[4], const uint32_t a[4],
                                         const uint32_t b0, const uint32_t b1) {
    asm volatile(
        "mma.sync.aligned.m16n8k16.row.col.f32.bf16.bf16.f32 "
        "{%0,%1,%2,%3}, {%4,%5,%6,%7}, {%8,%9}, {%0,%1,%2,%3};"
        : "+f"(c[0]), "+f"(c[1]), "+f"(c[2]), "+f"(c[3])
        : "r"(a[0]), "r"(a[1]), "r"(a[2]), "r"(a[3]), "r"(b0), "r"(b1));
}

// ---------------- split fp32 -> (bf16 hi, bf16 lo) ------------------------
template<int SEL>
__global__ void __launch_bounds__(256) split_kernel(const float4* __restrict__ in, int n4)
{
    int i = blockIdx.x * 256 + threadIdx.x;
    if (i >= n4) return;
    __nv_bfloat16* o0 = SEL == 0 ? g_x0 : SEL == 1 ? g_wi0 : g_wo0;
    __nv_bfloat16* o1 = SEL == 0 ? g_x1 : SEL == 1 ? g_wi1 : g_wo1;
    float4 v = in[i];
    float f[4] = {v.x, v.y, v.z, v.w};
#pragma unroll
    for (int j = 0; j < 4; j++) {
        __nv_bfloat16 h0 = __float2bfloat16(f[j]);
        o0[4 * i + j] = h0;
        o1[4 * i + j] = __float2bfloat16(f[j] - __bfloat162float(h0));
    }
}

// ---------------- mma.sync bf16x3 GEMM: C[M,N] = A @ B^T ------------------
// Block tile 128x128, K-slab 64, 8 warps (warp tile 32x64), double buffer.
// EPI=0: A=x(split), B=w_in(split), epilogue scatters q/k/v (fp32)
// EPI=1: A=o(split), B=w_out(split), epilogue adds bias -> Cout
#define KSLAB 64
#define NCH (D / KSLAB)        /* 32 */
#define TILE_BYTES (128 * 128) /* 128 rows x 128B */
#define ST_A0 0
#define ST_A1 (1 * TILE_BYTES)
#define ST_B0 (2 * TILE_BYTES)
#define ST_B1 (3 * TILE_BYTES)
#define STAGE_BYTES (4 * TILE_BYTES)   /* 64 KB */
#define GEMM_DYN (2 * STAGE_BYTES + 1024)

// swizzled byte offset within a tile: row in [0,128), ch = 16B chunk in [0,8)
__device__ __forceinline__ uint32_t swz(int row, int ch) {
    return (uint32_t)(row * 128 + (((ch) << 4) ^ ((row & 7) << 4)));
}

template<int EPI>
__global__ void __launch_bounds__(256) gemm_mma(const float* __restrict__ bias,
                                                float* __restrict__ Cout)
{
    extern __shared__ char dsm[];
    const uint32_t base = (smem_to_u32(dsm) + 1023u) & ~1023u;
    const int tid = threadIdx.x, lane = tid & 31, wid = tid >> 5;
    const int wm = wid >> 1, wn = wid & 1;
    const int row0 = blockIdx.y * 128, col0 = blockIdx.x * 128;

    const __nv_bfloat16* A0 = EPI == 0 ? g_x0  : g_o0;
    const __nv_bfloat16* A1 = EPI == 0 ? g_x1  : g_o1;
    const __nv_bfloat16* B0 = EPI == 0 ? g_wi0 : g_wo0;
    const __nv_bfloat16* B1 = EPI == 0 ? g_wi1 : g_wo1;

    float acc[2][8][4] = {};

    auto load_stage = [&](int c, int s) {
        const uint32_t sb = base + s * STAGE_BYTES;
        const int k0 = c * KSLAB;
        const int ch = tid & 7;
        const int rb = tid >> 3;            // 0..31
#pragma unroll
        for (int i = 0; i < 16; i++) {
            const int tile = i >> 2;
            const int r = rb + 32 * (i & 3);
            const uint32_t dst = sb + tile * TILE_BYTES + swz(r, ch);
            const __nv_bfloat16* src;
            if (tile == 0)      src = A0 + (size_t)(row0 + r) * D + k0 + ch * 8;
            else if (tile == 1) src = A1 + (size_t)(row0 + r) * D + k0 + ch * 8;
            else if (tile == 2) src = B0 + (size_t)(col0 + r) * D + k0 + ch * 8;
            else                src = B1 + (size_t)(col0 + r) * D + k0 + ch * 8;
            CP_ASYNC16(dst, src);
        }
    };

    load_stage(0, 0);
    CP_COMMIT();

    for (int c = 0; c < NCH; c++) {
        if (c + 1 < NCH) {
            load_stage(c + 1, (c + 1) & 1);
            CP_COMMIT();
            CP_WAIT(1);
        } else {
            CP_WAIT(0);
        }
        __syncthreads();

        const uint32_t sb = base + (c & 1) * STAGE_BYTES;
#pragma unroll
        for (int kk = 0; kk < 4; kk++) {
            uint32_t a0f[2][4], a1f[2][4], b0f[4][4], b1f[4][4];
#pragma unroll
            for (int mt = 0; mt < 2; mt++) {
                int row = wm * 32 + mt * 16 + (lane & 7) + ((lane >> 3) & 1) * 8;
                int chv = 2 * kk + (lane >> 4);
                uint32_t ad = sb + ST_A0 + swz(row, chv);
                ldsm4(a0f[mt], ad);
                ldsm4(a1f[mt], ad + (ST_A1 - ST_A0));
            }
#pragma unroll
            for (int ng = 0; ng < 4; ng++) {
                int row = wn * 64 + ng * 16 + (lane & 7) + (lane >> 4) * 8;
                int chv = 2 * kk + ((lane >> 3) & 1);
                uint32_t bd = sb + ST_B0 + swz(row, chv);
                ldsm4(b0f[ng], bd);
                ldsm4(b1f[ng], bd + (ST_B1 - ST_B0));
            }
#pragma unroll
            for (int mt = 0; mt < 2; mt++)
#pragma unroll
                for (int ng = 0; ng < 4; ng++) {
                    mma16816(acc[mt][2 * ng],     a0f[mt], b0f[ng][0], b0f[ng][1]);
                    mma16816(acc[mt][2 * ng + 1], a0f[mt], b0f[ng][2], b0f[ng][3]);
                    mma16816(acc[mt][2 * ng],     a0f[mt], b1f[ng][0], b1f[ng][1]);
                    mma16816(acc[mt][2 * ng + 1], a0f[mt], b1f[ng][2], b1f[ng][3]);
                    mma16816(acc[mt][2 * ng],     a1f[mt], b0f[ng][0], b0f[ng][1]);
                    mma16816(acc[mt][2 * ng + 1], a1f[mt], b0f[ng][2], b0f[ng][3]);
                }
        }
        __syncthreads();
    }

    // epilogue
    const int g = lane >> 2, tig = lane & 3;
#pragma unroll
    for (int mt = 0; mt < 2; mt++) {
#pragma unroll
        for (int nt = 0; nt < 8; nt++) {
            int colg = col0 + wn * 64 + nt * 8 + 2 * tig;
            int mA = row0 + wm * 32 + mt * 16 + g;
            int mB = mA + 8;
            float2 vA = make_float2(acc[mt][nt][0], acc[mt][nt][1]);
            float2 vB = make_float2(acc[mt][nt][2], acc[mt][nt][3]);
            if (EPI == 0) {
                int which = colg >> 11, hh = (colg >> 7) & 15, d0 = colg & 127;
                float* t = which == 0 ? g_q : (which == 1 ? g_k : g_v);
                int bbA = mA >> 10, srA = mA & 1023;
                int bbB = mB >> 10, srB = mB & 1023;
                *(float2*)&t[((size_t)(bbA * H + hh) * NS + srA) * DHD + d0] = vA;
                *(float2*)&t[((size_t)(bbB * H + hh) * NS + srB) * DHD + d0] = vB;
            } else {
                float b0v = bias[colg], b1v = bias[colg + 1];
                vA.x += b0v; vA.y += b1v;
                vB.x += b0v; vB.y += b1v;
                *(float2*)&Cout[(size_t)mA * D + colg] = vA;
                *(float2*)&Cout[(size_t)mB * D + colg] = vB;
            }
        }
    }
}

// ---------------- attention: flash-style fp32 SIMT ------------------------
#define BQ 64
#define BK 64
#define QLD 129
#define KLD 129
#define SLD 65
#define ATTN_SMEM_FLOATS (BQ * QLD + BK * KLD + BK * DHD + BQ * SLD + 4 * 64)
#define ATTN_SMEM_BYTES (ATTN_SMEM_FLOATS * 4)

__global__ void __launch_bounds__(256) attn_kernel(const int* __restrict__ ids)
{
    extern __shared__ float sm[];
    float* Qs   = sm;
    float* Ks   = Qs + BQ * QLD;
    float* Vs   = Ks + BK * KLD;
    float* Ss   = Vs + BK * DHD;
    float* mrow = Ss + BQ * SLD;
    float* lrow = mrow + BQ;
    float* crow = lrow + BQ;
    float* bks  = crow + BQ;

    const int tid = threadIdx.x;
    const int ty = tid >> 4;
    const int tx = tid & 15;
    const int qt = blockIdx.x;
    const int h  = blockIdx.y;
    const int b  = blockIdx.z;

    const float* Qg = g_q + ((size_t)(b * H + h) * NS + qt * BQ) * DHD;
    const float* Kg = g_k + ((size_t)(b * H + h) * NS) * DHD;
    const float* Vg = g_v + ((size_t)(b * H + h) * NS) * DHD;

#pragma unroll
    for (int r = 0; r < 8; r++) {
        int idx = tid + 256 * r;
        int s = idx >> 5;
        int d4 = (idx & 31) << 2;
        float4 v = *(const float4*)&Qg[s * DHD + d4];
        Qs[s * QLD + d4 + 0] = v.x;
        Qs[s * QLD + d4 + 1] = v.y;
        Qs[s * QLD + d4 + 2] = v.z;
        Qs[s * QLD + d4 + 3] = v.w;
    }
    if (tid < BQ) { mrow[tid] = -1e30f; lrow[tid] = 0.0f; }

    float oacc[4][8] = {};

    for (int kt = 0; kt < NS / BK; kt++) {
        __syncthreads();
#pragma unroll
        for (int r = 0; r < 8; r++) {
            int idx = tid + 256 * r;
            int s = idx >> 5;
            int d4 = (idx & 31) << 2;
            float4 kv = *(const float4*)&Kg[(kt * BK + s) * DHD + d4];
            Ks[s * KLD + d4 + 0] = kv.x;
            Ks[s * KLD + d4 + 1] = kv.y;
            Ks[s * KLD + d4 + 2] = kv.z;
            Ks[s * KLD + d4 + 3] = kv.w;
            float4 vv = *(const float4*)&Vg[(kt * BK + s) * DHD + d4];
            *(float4*)&Vs[s * DHD + d4] = vv;
        }
        if (tid < BK)
            bks[tid] = MASK_BIAS * (float)ids[b * NS + kt * BK + tid];
        __syncthreads();

        float sacc[4][4] = {};
#pragma unroll 4
        for (int d = 0; d < DHD; d++) {
            float qv[4], kv[4];
#pragma unroll
            for (int i = 0; i < 4; i++) qv[i] = Qs[(4 * ty + i) * QLD + d];
#pragma unroll
            for (int j = 0; j < 4; j++) kv[j] = Ks[(4 * tx + j) * KLD + d];
#pragma unroll
            for (int i = 0; i < 4; i++)
#pragma unroll
                for (int j = 0; j < 4; j++)
                    sacc[i][j] += qv[i] * kv[j];
        }
#pragma unroll
        for (int i = 0; i < 4; i++)
#pragma unroll
            for (int j = 0; j < 4; j++)
                Ss[(4 * ty + i) * SLD + 4 * tx + j] =
                    (sacc[i][j] + bks[4 * tx + j]) * SCALE;
        __syncthreads();

        if (tid < BQ) {
            int r = tid;
            float mold = mrow[r];
            float mmax = mold;
            for (int c = 0; c < BK; c++)
                mmax = fmaxf(mmax, Ss[r * SLD + c]);
            float corr = __expf(mold - mmax);
            float lsum = 0.0f;
            for (int c = 0; c < BK; c++) {
                float p = __expf(Ss[r * SLD + c] - mmax);
                Ss[r * SLD + c] = p;
                lsum += p;
            }
            mrow[r] = mmax;
            lrow[r] = lrow[r] * corr + lsum;
            crow[r] = corr;
        }
        __syncthreads();

#pragma unroll
        for (int i = 0; i < 4; i++) {
            float corr = crow[4 * ty + i];
#pragma unroll
            for (int j = 0; j < 8; j++) oacc[i][j] *= corr;
        }
#pragma unroll 4
        for (int kr = 0; kr < BK; kr++) {
            float pv[4];
#pragma unroll
            for (int i = 0; i < 4; i++) pv[i] = Ss[(4 * ty + i) * SLD + kr];
            float4 v0 = *(float4*)&Vs[kr * DHD + 8 * tx];
            float4 v1 = *(float4*)&Vs[kr * DHD + 8 * tx + 4];
#pragma unroll
            for (int i = 0; i < 4; i++) {
                oacc[i][0] += pv[i] * v0.x;
                oacc[i][1] += pv[i] * v0.y;
                oacc[i][2] += pv[i] * v0.z;
                oacc[i][3] += pv[i] * v0.w;
                oacc[i][4] += pv[i] * v1.x;
                oacc[i][5] += pv[i] * v1.y;
                oacc[i][6] += pv[i] * v1.z;
                oacc[i][7] += pv[i] * v1.w;
            }
        }
    }

    // epilogue: write bf16 hi/lo split of o directly (GEMM2 A operand)
    __nv_bfloat16* O0 = g_o0 + (size_t)(b * NS + qt * BQ) * D + h * DHD;
    __nv_bfloat16* O1 = g_o1 + (size_t)(b * NS + qt * BQ) * D + h * DHD;
#pragma unroll
    for (int i = 0; i < 4; i++) {
        int r = 4 * ty + i;
        float linv = 1.0f / lrow[r];
#pragma unroll
        for (int jj = 0; jj < 8; jj++) {
            float v = oacc[i][jj] * linv;
            __nv_bfloat16 h0 = __float2bfloat16(v);
            O0[(size_t)r * D + 8 * tx + jj] = h0;
            O1[(size_t)r * D + 8 * tx + jj] =
                __float2bfloat16(v - __bfloat162float(h0));
        }
    }
}

// ---------------- launch ---------------------------------------------------
extern "C" void kernel_launch(void* const* d_in, const int* in_sizes, int n_in,
                              void* d_out, int out_size)
{
    const float* x     = (const float*)d_in[0];
    const int*   ids   = (const int*)d_in[1];
    const float* w_in  = (const float*)d_in[2];
    const float* w_out = (const float*)d_in[3];
    const float* b_out = (const float*)d_in[4];
    float* out = (float*)d_out;

    cudaFuncSetAttribute(gemm_mma<0>,
                         cudaFuncAttributeMaxDynamicSharedMemorySize, GEMM_DYN);
    cudaFuncSetAttribute(gemm_mma<1>,
                         cudaFuncAttributeMaxDynamicSharedMemorySize, GEMM_DYN);
    cudaFuncSetAttribute(attn_kernel,
                         cudaFuncAttributeMaxDynamicSharedMemorySize, ATTN_SMEM_BYTES);

    const int NX  = M_ROWS * D;
    const int NWI = N_QKV * D;
    const int NWO = D * D;
    split_kernel<0><<<NX  / 1024, 256>>>((const float4*)x,     NX  / 4);
    split_kernel<1><<<NWI / 1024, 256>>>((const float4*)w_in,  NWI / 4);
    split_kernel<2><<<NWO / 1024, 256>>>((const float4*)w_out, NWO / 4);

    gemm_mma<0><<<dim3(N_QKV / 128, M_ROWS / 128), 256, GEMM_DYN>>>(nullptr, nullptr);
    attn_kernel<<<dim3(NS / BQ, H, BS), 256, ATTN_SMEM_BYTES>>>(ids);
    gemm_mma<1><<<dim3(D / 128, M_ROWS / 128), 256, GEMM_DYN>>>(b_out, out);
}

// round 4
// speedup vs baseline: 3.2590x; 1.6741x over previous
#include <cuda_runtime.h>
#include <cuda_bf16.h>
#include <cstdint>

#define BS 4
#define NS 1024
#define D 2048
#define H 16
#define DHD 128
#define SCALE 0.08838834764831845f
#define MASK_BIAS -1e9f
#define M_ROWS (BS * NS)   /* 4096 */
#define N_QKV (3 * D)      /* 6144 */

// ---------------- scratch (static device globals; no allocation) ----------
__device__ __nv_bfloat16 g_x0[M_ROWS * D],  g_x1[M_ROWS * D];
__device__ __nv_bfloat16 g_wi0[N_QKV * D],  g_wi1[N_QKV * D];
__device__ __nv_bfloat16 g_wo0[D * D],      g_wo1[D * D];
__device__ __nv_bfloat16 g_o0[M_ROWS * D],  g_o1[M_ROWS * D];
// q,k: [b,h,seq,dh]; v: TRANSPOSED [b,h,dh,seq]
__device__ __nv_bfloat16 g_q0[BS*H*NS*DHD], g_q1[BS*H*NS*DHD];
__device__ __nv_bfloat16 g_k0[BS*H*NS*DHD], g_k1[BS*H*NS*DHD];
__device__ __nv_bfloat16 g_v0[BS*H*NS*DHD], g_v1[BS*H*NS*DHD];

// ---------------- helpers ---------------------------------------------------
__device__ __forceinline__ uint32_t smem_to_u32(const void* p) {
    uint32_t a;
    asm("{ .reg .u64 t; cvta.to.shared.u64 t, %1; cvt.u32.u64 %0, t; }"
        : "=r"(a) : "l"(p));
    return a;
}
#define CP_ASYNC16(dst, src) \
    asm volatile("cp.async.cg.shared.global [%0], [%1], 16;" \
                 :: "r"((uint32_t)(dst)), "l"(src) : "memory")
#define CP_COMMIT() asm volatile("cp.async.commit_group;" ::: "memory")
#define CP_WAIT(n)  asm volatile("cp.async.wait_group %0;" :: "n"(n) : "memory")

__device__ __forceinline__ void ldsm4(uint32_t r[4], uint32_t addr) {
    asm volatile("ldmatrix.sync.aligned.m8n8.x4.shared.b16 {%0,%1,%2,%3}, [%4];"
                 : "=r"(r[0]), "=r"(r[1]), "=r"(r[2]), "=r"(r[3]) : "r"(addr));
}
__device__ __forceinline__ void mma16816(float c[4], const uint32_t a[4],
                                         const uint32_t b0, const uint32_t b1) {
    asm volatile(
        "mma.sync.aligned.m16n8k16.row.col.f32.bf16.bf16.f32 "
        "{%0,%1,%2,%3}, {%4,%5,%6,%7}, {%8,%9}, {%0,%1,%2,%3};"
        : "+f"(c[0]), "+f"(c[1]), "+f"(c[2]), "+f"(c[3])
        : "r"(a[0]), "r"(a[1]), "r"(a[2]), "r"(a[3]), "r"(b0), "r"(b1));
}
__device__ __forceinline__ uint32_t packb(__nv_bfloat16 a, __nv_bfloat16 b) {
    __nv_bfloat162 t(a, b);
    return *reinterpret_cast<uint32_t*>(&t);
}
// swizzles: 128B rows (8 x 16B chunks), 256B rows (16 x 16B chunks)
__device__ __forceinline__ uint32_t swz128(int row, int ch) {
    return (uint32_t)(row * 128 + ((ch ^ (row & 7)) << 4));
}
__device__ __forceinline__ uint32_t swz256(int row, int ch) {
    return (uint32_t)(row * 256 + ((ch ^ ((row & 7) << 1)) << 4));
}

// ---------------- split fp32 -> (bf16 hi, bf16 lo) ------------------------
template<int SEL>
__global__ void __launch_bounds__(256) split_kernel(const float4* __restrict__ in, int n4)
{
    int i = blockIdx.x * 256 + threadIdx.x;
    if (i >= n4) return;
    __nv_bfloat16* o0 = SEL == 0 ? g_x0 : SEL == 1 ? g_wi0 : g_wo0;
    __nv_bfloat16* o1 = SEL == 0 ? g_x1 : SEL == 1 ? g_wi1 : g_wo1;
    float4 v = in[i];
    float f[4] = {v.x, v.y, v.z, v.w};
#pragma unroll
    for (int j = 0; j < 4; j++) {
        __nv_bfloat16 h0 = __float2bfloat16(f[j]);
        o0[4 * i + j] = h0;
        o1[4 * i + j] = __float2bfloat16(f[j] - __bfloat162float(h0));
    }
}

// ---------------- mma.sync bf16x3 GEMM: C[M,N] = A @ B^T ------------------
// 128x128 tile, K-slab 64, 8 warps, 3-stage cp.async pipeline.
#define KSLAB 64
#define NCH (D / KSLAB)        /* 32 */
#define TILE_BYTES (128 * 128)
#define ST_A0 0
#define ST_A1 (1 * TILE_BYTES)
#define ST_B0 (2 * TILE_BYTES)
#define ST_B1 (3 * TILE_BYTES)
#define STAGE_BYTES (4 * TILE_BYTES)   /* 64 KB */
#define GEMM_DYN (3 * STAGE_BYTES + 1024)

template<int EPI>
__global__ void __launch_bounds__(256) gemm_mma(const float* __restrict__ bias,
                                                float* __restrict__ Cout)
{
    extern __shared__ char dsm[];
    const uint32_t base = (smem_to_u32(dsm) + 1023u) & ~1023u;
    const int tid = threadIdx.x, lane = tid & 31, wid = tid >> 5;
    const int wm = wid >> 1, wn = wid & 1;
    const int row0 = blockIdx.y * 128, col0 = blockIdx.x * 128;

    const __nv_bfloat16* A0 = EPI == 0 ? g_x0  : g_o0;
    const __nv_bfloat16* A1 = EPI == 0 ? g_x1  : g_o1;
    const __nv_bfloat16* B0 = EPI == 0 ? g_wi0 : g_wo0;
    const __nv_bfloat16* B1 = EPI == 0 ? g_wi1 : g_wo1;

    float acc[2][8][4] = {};

    auto load_stage = [&](int c, int s) {
        const uint32_t sb = base + s * STAGE_BYTES;
        const int k0 = c * KSLAB;
        const int ch = tid & 7;
        const int rb = tid >> 3;
#pragma unroll
        for (int i = 0; i < 16; i++) {
            const int tile = i >> 2;
            const int r = rb + 32 * (i & 3);
            const uint32_t dst = sb + tile * TILE_BYTES + swz128(r, ch);
            const __nv_bfloat16* src;
            if (tile == 0)      src = A0 + (size_t)(row0 + r) * D + k0 + ch * 8;
            else if (tile == 1) src = A1 + (size_t)(row0 + r) * D + k0 + ch * 8;
            else if (tile == 2) src = B0 + (size_t)(col0 + r) * D + k0 + ch * 8;
            else                src = B1 + (size_t)(col0 + r) * D + k0 + ch * 8;
            CP_ASYNC16(dst, src);
        }
    };

    load_stage(0, 0); CP_COMMIT();
    load_stage(1, 1); CP_COMMIT();

    for (int c = 0; c < NCH; c++) {
        if (c == NCH - 1) { CP_WAIT(0); } else { CP_WAIT(1); }
        __syncthreads();
        if (c + 2 < NCH) { load_stage(c + 2, (c + 2) % 3); CP_COMMIT(); }

        const uint32_t sb = base + (c % 3) * STAGE_BYTES;
#pragma unroll
        for (int kk = 0; kk < 4; kk++) {
            uint32_t a0f[2][4], a1f[2][4], b0f[4][4], b1f[4][4];
#pragma unroll
            for (int mt = 0; mt < 2; mt++) {
                int row = wm * 32 + mt * 16 + (lane & 7) + ((lane >> 3) & 1) * 8;
                int chv = 2 * kk + (lane >> 4);
                uint32_t ad = sb + ST_A0 + swz128(row, chv);
                ldsm4(a0f[mt], ad);
                ldsm4(a1f[mt], ad + (ST_A1 - ST_A0));
            }
#pragma unroll
            for (int ng = 0; ng < 4; ng++) {
                int row = wn * 64 + ng * 16 + (lane & 7) + (lane >> 4) * 8;
                int chv = 2 * kk + ((lane >> 3) & 1);
                uint32_t bd = sb + ST_B0 + swz128(row, chv);
                ldsm4(b0f[ng], bd);
                ldsm4(b1f[ng], bd + (ST_B1 - ST_B0));
            }
#pragma unroll
            for (int mt = 0; mt < 2; mt++)
#pragma unroll
                for (int ng = 0; ng < 4; ng++) {
                    mma16816(acc[mt][2 * ng],     a0f[mt], b0f[ng][0], b0f[ng][1]);
                    mma16816(acc[mt][2 * ng + 1], a0f[mt], b0f[ng][2], b0f[ng][3]);
                    mma16816(acc[mt][2 * ng],     a0f[mt], b1f[ng][0], b1f[ng][1]);
                    mma16816(acc[mt][2 * ng + 1], a0f[mt], b1f[ng][2], b1f[ng][3]);
                    mma16816(acc[mt][2 * ng],     a1f[mt], b0f[ng][0], b0f[ng][1]);
                    mma16816(acc[mt][2 * ng + 1], a1f[mt], b0f[ng][2], b0f[ng][3]);
                }
        }
        __syncthreads();
    }

    // epilogue
    const int g = lane >> 2, tig = lane & 3;
#pragma unroll
    for (int mt = 0; mt < 2; mt++) {
#pragma unroll
        for (int nt = 0; nt < 8; nt++) {
            int colg = col0 + wn * 64 + nt * 8 + 2 * tig;
            int mA = row0 + wm * 32 + mt * 16 + g;
            int mB = mA + 8;
            float2 vA = make_float2(acc[mt][nt][0], acc[mt][nt][1]);
            float2 vB = make_float2(acc[mt][nt][2], acc[mt][nt][3]);
            if (EPI == 0) {
                int which = colg >> 11, hh = (colg >> 7) & 15, d0 = colg & 127;
                int bbA = mA >> 10, srA = mA & 1023;
                int bbB = mB >> 10, srB = mB & 1023;
                __nv_bfloat16 hAx = __float2bfloat16(vA.x), hAy = __float2bfloat16(vA.y);
                __nv_bfloat16 hBx = __float2bfloat16(vB.x), hBy = __float2bfloat16(vB.y);
                __nv_bfloat16 lAx = __float2bfloat16(vA.x - __bfloat162float(hAx));
                __nv_bfloat16 lAy = __float2bfloat16(vA.y - __bfloat162float(hAy));
                __nv_bfloat16 lBx = __float2bfloat16(vB.x - __bfloat162float(hBx));
                __nv_bfloat16 lBy = __float2bfloat16(vB.y - __bfloat162float(hBy));
                if (which < 2) {
                    __nv_bfloat16* p0 = which ? g_k0 : g_q0;
                    __nv_bfloat16* p1 = which ? g_k1 : g_q1;
                    size_t iA = ((size_t)(bbA * H + hh) * NS + srA) * DHD + d0;
                    size_t iB = ((size_t)(bbB * H + hh) * NS + srB) * DHD + d0;
                    *(uint32_t*)&p0[iA] = packb(hAx, hAy);
                    *(uint32_t*)&p1[iA] = packb(lAx, lAy);
                    *(uint32_t*)&p0[iB] = packb(hBx, hBy);
                    *(uint32_t*)&p1[iB] = packb(lBx, lBy);
                } else {
                    // v transposed: [b,h,dh,seq]
                    size_t bA = ((size_t)(bbA * H + hh)) * DHD * NS;
                    size_t bB = ((size_t)(bbB * H + hh)) * DHD * NS;
                    g_v0[bA + (size_t)d0 * NS + srA]       = hAx;
                    g_v0[bA + (size_t)(d0 + 1) * NS + srA] = hAy;
                    g_v1[bA + (size_t)d0 * NS + srA]       = lAx;
                    g_v1[bA + (size_t)(d0 + 1) * NS + srA] = lAy;
                    g_v0[bB + (size_t)d0 * NS + srB]       = hBx;
                    g_v0[bB + (size_t)(d0 + 1) * NS + srB] = hBy;
                    g_v1[bB + (size_t)d0 * NS + srB]       = lBx;
                    g_v1[bB + (size_t)(d0 + 1) * NS + srB] = lBy;
                }
            } else {
                float b0v = bias[colg], b1v = bias[colg + 1];
                vA.x += b0v; vA.y += b1v;
                vB.x += b0v; vB.y += b1v;
                *(float2*)&Cout[(size_t)mA * D + colg] = vA;
                *(float2*)&Cout[(size_t)mB * D + colg] = vB;
            }
        }
    }
}

// ---------------- attention: flash, mma.sync bf16x3 -----------------------
// CTA: 128 q-rows x one (b,h). 8 warps x 16 rows. K-tile 64.
// smem: Q hi/lo [128][256B], per-stage K hi/lo [64][256B] + VT hi/lo [128][128B]
#define AQ0_OFF 0
#define AQ1_OFF 32768
#define AK_OFF(s) (65536 + (s) * 32768)   /* K0; K1 at +16384 */
#define AV_OFF(s) (131072 + (s) * 32768)  /* V0; V1 at +16384 */
#define ATTN_DYN (196608 + 1024)

__global__ void __launch_bounds__(256) attn_mma(const int* __restrict__ ids)
{
    extern __shared__ char dsm[];
    const uint32_t base = (smem_to_u32(dsm) + 1023u) & ~1023u;
    const int tid = threadIdx.x, lane = tid & 31, wid = tid >> 5;
    const int g = lane >> 2, tig = lane & 3;
    const int qt = blockIdx.x, h = blockIdx.y, b = blockIdx.z;
    const int bh = b * H + h;
    const size_t qk_base = (size_t)bh * NS * DHD;

    // ---- async loads ----
    auto load_q = [&]() {
        const int qrow0 = qt * 128;
#pragma unroll
        for (int i = 0; i < 16; i++) {
            int idx = tid + 256 * i;           // 4096 16B-items
            int plane = idx >> 11;             // 0..1
            int r = (idx >> 4) & 127;
            int ch = idx & 15;
            const __nv_bfloat16* src = (plane ? g_q1 : g_q0) +
                qk_base + (size_t)(qrow0 + r) * DHD + ch * 8;
            CP_ASYNC16(base + (plane ? AQ1_OFF : AQ0_OFF) + swz256(r, ch), src);
        }
    };
    auto load_kv = [&](int kt, int s) {
#pragma unroll
        for (int i = 0; i < 8; i++) {          // K: 2048 items
            int idx = tid + 256 * i;
            int plane = idx >> 10;
            int r = (idx >> 4) & 63;
            int ch = idx & 15;
            const __nv_bfloat16* src = (plane ? g_k1 : g_k0) +
                qk_base + (size_t)(kt * 64 + r) * DHD + ch * 8;
            CP_ASYNC16(base + AK_OFF(s) + plane * 16384 + swz256(r, ch), src);
        }
#pragma unroll
        for (int i = 0; i < 8; i++) {          // VT: 2048 items
            int idx = tid + 256 * i;
            int plane = idx >> 10;
            int r = (idx >> 3) & 127;          // dh row
            int ch = idx & 7;
            const __nv_bfloat16* src = (plane ? g_v1 : g_v0) +
                (size_t)bh * DHD * NS + (size_t)r * NS + kt * 64 + ch * 8;
            CP_ASYNC16(base + AV_OFF(s) + plane * 16384 + swz128(r, ch), src);
        }
    };

    load_q(); load_kv(0, 0); CP_COMMIT();
    load_kv(1, 1); CP_COMMIT();

    // lane-invariant frag address components
    const int a_row = wid * 16 + (lane & 7) + ((lane >> 3) & 1) * 8; // Q rows
    const int a_chh = lane >> 4;
    const int b_rowl = (lane & 7) + (lane >> 4) * 8;                 // B rows
    const int b_chh = (lane >> 3) & 1;

    float m0 = -1e30f, m1 = -1e30f, l0 = 0.f, l1 = 0.f;
    float o[16][4] = {};

    const int ids_base = b * NS;

    for (int kt = 0; kt < 16; kt++) {
        if (kt + 1 < 16) { CP_WAIT(1); } else { CP_WAIT(0); }
        __syncthreads();

        const uint32_t sbK = base + AK_OFF(kt & 1);
        const uint32_t sbV = base + AV_OFF(kt & 1);

        // ---- S = Q @ K^T (bf16x3) ----
        float s[8][4] = {};
#pragma unroll
        for (int kk = 0; kk < 8; kk++) {
            uint32_t aq0[4], aq1[4];
            uint32_t ad = base + swz256(a_row, 2 * kk + a_chh);
            ldsm4(aq0, ad + AQ0_OFF);
            ldsm4(aq1, ad + AQ1_OFF);
#pragma unroll
            for (int ng = 0; ng < 4; ng++) {
                uint32_t k0f[4], k1f[4];
                uint32_t bd = sbK + swz256(ng * 16 + b_rowl, 2 * kk + b_chh);
                ldsm4(k0f, bd);
                ldsm4(k1f, bd + 16384);
                mma16816(s[2 * ng],     aq0, k0f[0], k0f[1]);
                mma16816(s[2 * ng + 1], aq0, k0f[2], k0f[3]);
                mma16816(s[2 * ng],     aq0, k1f[0], k1f[1]);
                mma16816(s[2 * ng + 1], aq0, k1f[2], k1f[3]);
                mma16816(s[2 * ng],     aq1, k0f[0], k0f[1]);
                mma16816(s[2 * ng + 1], aq1, k0f[2], k0f[3]);
            }
        }

        // ---- bias + scale + online softmax ----
        float mx0 = -1e30f, mx1 = -1e30f;
#pragma unroll
        for (int j = 0; j < 8; j++) {
            int c = kt * 64 + 8 * j + 2 * tig;
            float bc0 = MASK_BIAS * (float)__ldg(&ids[ids_base + c]);
            float bc1 = MASK_BIAS * (float)__ldg(&ids[ids_base + c + 1]);
            s[j][0] = (s[j][0] + bc0) * SCALE;
            s[j][1] = (s[j][1] + bc1) * SCALE;
            s[j][2] = (s[j][2] + bc0) * SCALE;
            s[j][3] = (s[j][3] + bc1) * SCALE;
            mx0 = fmaxf(mx0, fmaxf(s[j][0], s[j][1]));
            mx1 = fmaxf(mx1, fmaxf(s[j][2], s[j][3]));
        }
        mx0 = fmaxf(mx0, __shfl_xor_sync(0xFFFFFFFF, mx0, 1));
        mx0 = fmaxf(mx0, __shfl_xor_sync(0xFFFFFFFF, mx0, 2));
        mx1 = fmaxf(mx1, __shfl_xor_sync(0xFFFFFFFF, mx1, 1));
        mx1 = fmaxf(mx1, __shfl_xor_sync(0xFFFFFFFF, mx1, 2));
        float m0n = fmaxf(m0, mx0), m1n = fmaxf(m1, mx1);
        float c0 = __expf(m0 - m0n), c1 = __expf(m1 - m1n);
        m0 = m0n; m1 = m1n;
        float ls0 = 0.f, ls1 = 0.f;
#pragma unroll
        for (int j = 0; j < 8; j++) {
            s[j][0] = __expf(s[j][0] - m0);
            s[j][1] = __expf(s[j][1] - m0);
            s[j][2] = __expf(s[j][2] - m1);
            s[j][3] = __expf(s[j][3] - m1);
            ls0 += s[j][0] + s[j][1];
            ls1 += s[j][2] + s[j][3];
        }
        ls0 += __shfl_xor_sync(0xFFFFFFFF, ls0, 1);
        ls0 += __shfl_xor_sync(0xFFFFFFFF, ls0, 2);
        ls1 += __shfl_xor_sync(0xFFFFFFFF, ls1, 1);
        ls1 += __shfl_xor_sync(0xFFFFFFFF, ls1, 2);
        l0 = l0 * c0 + ls0;
        l1 = l1 * c1 + ls1;
#pragma unroll
        for (int nt = 0; nt < 16; nt++) {
            o[nt][0] *= c0; o[nt][1] *= c0;
            o[nt][2] *= c1; o[nt][3] *= c1;
        }

        // ---- O += P @ V (bf16x3, P split in registers) ----
#pragma unroll
        for (int kc = 0; kc < 4; kc++) {
            uint32_t ap0[4], ap1[4];
            {
                __nv_bfloat16 h00 = __float2bfloat16(s[2*kc][0]);
                __nv_bfloat16 h01 = __float2bfloat16(s[2*kc][1]);
                __nv_bfloat16 h02 = __float2bfloat16(s[2*kc][2]);
                __nv_bfloat16 h03 = __float2bfloat16(s[2*kc][3]);
                __nv_bfloat16 h10 = __float2bfloat16(s[2*kc+1][0]);
                __nv_bfloat16 h11 = __float2bfloat16(s[2*kc+1][1]);
                __nv_bfloat16 h12 = __float2bfloat16(s[2*kc+1][2]);
                __nv_bfloat16 h13 = __float2bfloat16(s[2*kc+1][3]);
                ap0[0] = packb(h00, h01);
                ap0[1] = packb(h02, h03);
                ap0[2] = packb(h10, h11);
                ap0[3] = packb(h12, h13);
                ap1[0] = packb(__float2bfloat16(s[2*kc][0]   - __bfloat162float(h00)),
                               __float2bfloat16(s[2*kc][1]   - __bfloat162float(h01)));
                ap1[1] = packb(__float2bfloat16(s[2*kc][2]   - __bfloat162float(h02)),
                               __float2bfloat16(s[2*kc][3]   - __bfloat162float(h03)));
                ap1[2] = packb(__float2bfloat16(s[2*kc+1][0] - __bfloat162float(h10)),
                               __float2bfloat16(s[2*kc+1][1] - __bfloat162float(h11)));
                ap1[3] = packb(__float2bfloat16(s[2*kc+1][2] - __bfloat162float(h12)),
                               __float2bfloat16(s[2*kc+1][3] - __bfloat162float(h13)));
            }
#pragma unroll
            for (int nv = 0; nv < 8; nv++) {
                uint32_t v0f[4], v1f[4];
                uint32_t bd = sbV + swz128(nv * 16 + b_rowl, 2 * kc + b_chh);
                ldsm4(v0f, bd);
                ldsm4(v1f, bd + 16384);
                mma16816(o[2 * nv],     ap0, v0f[0], v0f[1]);
                mma16816(o[2 * nv + 1], ap0, v0f[2], v0f[3]);
                mma16816(o[2 * nv],     ap0, v1f[0], v1f[1]);
                mma16816(o[2 * nv + 1], ap0, v1f[2], v1f[3]);
                mma16816(o[2 * nv],     ap1, v0f[0], v0f[1]);
                mma16816(o[2 * nv + 1], ap1, v0f[2], v0f[3]);
            }
        }
        __syncthreads();
        if (kt + 2 < 16) { load_kv(kt + 2, kt & 1); CP_COMMIT(); }
    }

    // ---- normalize + write o as bf16 hi/lo [b, seq, D] ----
    float il0 = 1.0f / l0, il1 = 1.0f / l1;
    const int r0 = qt * 128 + wid * 16 + g;
    const int r1 = r0 + 8;
#pragma unroll
    for (int nt = 0; nt < 16; nt++) {
        int dcol = h * DHD + nt * 8 + 2 * tig;
        float v0 = o[nt][0] * il0, v1 = o[nt][1] * il0;
        float w0 = o[nt][2] * il1, w1 = o[nt][3] * il1;
        __nv_bfloat16 hv0 = __float2bfloat16(v0), hv1 = __float2bfloat16(v1);
        __nv_bfloat16 hw0 = __float2bfloat16(w0), hw1 = __float2bfloat16(w1);
        size_t i0 = (size_t)(b * NS + r0) * D + dcol;
        size_t i1 = (size_t)(b * NS + r1) * D + dcol;
        *(uint32_t*)&g_o0[i0] = packb(hv0, hv1);
        *(uint32_t*)&g_o1[i0] = packb(__float2bfloat16(v0 - __bfloat162float(hv0)),
                                      __float2bfloat16(v1 - __bfloat162float(hv1)));
        *(uint32_t*)&g_o0[i1] = packb(hw0, hw1);
        *(uint32_t*)&g_o1[i1] = packb(__float2bfloat16(w0 - __bfloat162float(hw0)),
                                      __float2bfloat16(w1 - __bfloat162float(hw1)));
    }
}

// ---------------- launch ---------------------------------------------------
extern "C" void kernel_launch(void* const* d_in, const int* in_sizes, int n_in,
                              void* d_out, int out_size)
{
    const float* x     = (const float*)d_in[0];
    const int*   ids   = (const int*)d_in[1];
    const float* w_in  = (const float*)d_in[2];
    const float* w_out = (const float*)d_in[3];
    const float* b_out = (const float*)d_in[4];
    float* out = (float*)d_out;

    cudaFuncSetAttribute(gemm_mma<0>,
                         cudaFuncAttributeMaxDynamicSharedMemorySize, GEMM_DYN);
    cudaFuncSetAttribute(gemm_mma<1>,
                         cudaFuncAttributeMaxDynamicSharedMemorySize, GEMM_DYN);
    cudaFuncSetAttribute(attn_mma,
                         cudaFuncAttributeMaxDynamicSharedMemorySize, ATTN_DYN);

    const int NX  = M_ROWS * D;
    const int NWI = N_QKV * D;
    const int NWO = D * D;
    split_kernel<0><<<NX  / 1024, 256>>>((const float4*)x,     NX  / 4);
    split_kernel<1><<<NWI / 1024, 256>>>((const float4*)w_in,  NWI / 4);
    split_kernel<2><<<NWO / 1024, 256>>>((const float4*)w_out, NWO / 4);

    gemm_mma<0><<<dim3(N_QKV / 128, M_ROWS / 128), 256, GEMM_DYN>>>(nullptr, nullptr);
    attn_mma<<<dim3(NS / 128, H, BS), 256, ATTN_DYN>>>(ids);
    gemm_mma<1><<<dim3(D / 128, M_ROWS / 128), 256, GEMM_DYN>>>(b_out, out);
}